// round 15
// baseline (speedup 1.0000x reference)
#include <cuda_runtime.h>
#include <cuda_fp16.h>
#include <cstdint>

// ---------------- problem constants ----------------
#define BATCH 8
#define NHID 256
#define LEN 2048
#define NHEAD 8
#define HDIM 64
#define DQKV 512
#define DOUT 2048
#define MTOT (BATCH * LEN)   // 16384

// ---------------- GEMM tiling (128x128 CTA, 64x64 warp, 128 thr, 3 buffers) ----------------
#define BKP 16                // kp rows per chunk (= 32 k elements)
#define POB 136               // smem pitch (uint32)
#define OBSZ (BKP * POB)      // 2176 uint32 per buffer
#define EPPO 132              // out epilogue bounce pitch
#define SMEM_G3 (6 * OBSZ * 4)   // 52224 B (A0..A2, B0..B2); out epi half = 33792 B

// Scratch (allocation-free). Operands packed as half2 k-pairs: word[kp][col].
__device__ uint32_t g_xh[(size_t)(BATCH * NHID / 2) * LEN];   // [1024][2048]
__device__ uint32_t g_wqh[(NHID / 2) * DQKV];
__device__ uint32_t g_wkh[(NHID / 2) * DQKV];
__device__ uint32_t g_wvh[(NHID / 2) * DQKV];
__device__ uint32_t g_woh[(DQKV / 2) * DOUT];                 // [256][2048]
__device__ uint32_t g_qkvh[(size_t)MTOT * 768];               // fp16 q/k/v, d-pair words
__device__ uint32_t g_atth[(size_t)(DQKV / 2) * MTOT];        // [256][16384]

// ---------------- helpers ----------------
__device__ __forceinline__ uint32_t pkh2(float a, float b) {
    __half2 h = __floats2half2_rn(a, b);
    return *reinterpret_cast<uint32_t*>(&h);
}
__device__ __forceinline__ float2 uph2(uint32_t u) {
    __half2 h;
    *reinterpret_cast<uint32_t*>(&h) = u;
    return __half22float2(h);
}
__device__ __forceinline__ uint32_t smem_u32(const void* p) {
    uint32_t a;
    asm("{ .reg .u64 t; cvta.to.shared.u64 t, %1; cvt.u32.u64 %0, t; }" : "=r"(a) : "l"(p));
    return a;
}
__device__ __forceinline__ void cpa16(uint32_t dst, const void* src) {
    asm volatile("cp.async.cg.shared.global [%0], [%1], 16;" :: "r"(dst), "l"(src));
}
#define CP_COMMIT() asm volatile("cp.async.commit_group;" ::: "memory")
#define CP_WAIT(n)  asm volatile("cp.async.wait_group %0;" :: "n"(n) : "memory")

__device__ __forceinline__ void mma16(float& d0, float& d1, float& d2, float& d3,
                                      uint32_t a0, uint32_t a1, uint32_t a2, uint32_t a3,
                                      uint32_t b0, uint32_t b1) {
    asm volatile(
        "mma.sync.aligned.m16n8k16.row.col.f32.f16.f16.f32 "
        "{%0,%1,%2,%3}, {%4,%5,%6,%7}, {%8,%9}, {%0,%1,%2,%3};"
        : "+f"(d0), "+f"(d1), "+f"(d2), "+f"(d3)
        : "r"(a0), "r"(a1), "r"(a2), "r"(a3), "r"(b0), "r"(b1));
}

// ---- 64x64 warp-tile chunk (2 k16-steps = 16 kp) ----
__device__ __forceinline__ void mma_chunk64(const uint32_t* __restrict__ Ab,
                                            const uint32_t* __restrict__ Bb,
                                            float acc[4][8][4], int mw, int nw,
                                            int c, int g) {
#pragma unroll
    for (int ks = 0; ks < 2; ks++) {
        const int kb = ks * 8;
        uint32_t a[4][4];
#pragma unroll
        for (int fm = 0; fm < 4; fm++) {
            const uint32_t* p = Ab + (kb + c) * POB + mw + fm * 16 + g;
            a[fm][0] = p[0];
            a[fm][1] = p[8];
            a[fm][2] = p[4 * POB];
            a[fm][3] = p[4 * POB + 8];
        }
#pragma unroll
        for (int fn = 0; fn < 8; fn++) {
            const uint32_t* q = Bb + (kb + c) * POB + nw + fn * 8 + g;
            uint32_t b0 = q[0];
            uint32_t b1 = q[4 * POB];
#pragma unroll
            for (int fm = 0; fm < 4; fm++)
                mma16(acc[fm][fn][0], acc[fm][fn][1], acc[fm][fn][2], acc[fm][fn][3],
                      a[fm][0], a[fm][1], a[fm][2], a[fm][3], b0, b1);
        }
    }
}

// ---------------- prep: pack fp32 [K][N] -> half2-k-pair words [K/2][N] ----------------
__device__ __forceinline__ void pack_item(const float* __restrict__ src,
                                          uint32_t* __restrict__ dst,
                                          int cols, int i) {
    int kp = i / (cols / 4);
    int c4 = (i % (cols / 4)) * 4;
    const float4 r0 = *(const float4*)(src + (size_t)(2 * kp) * cols + c4);
    const float4 r1 = *(const float4*)(src + (size_t)(2 * kp + 1) * cols + c4);
    uint4 o;
    o.x = pkh2(r0.x, r1.x);
    o.y = pkh2(r0.y, r1.y);
    o.z = pkh2(r0.z, r1.z);
    o.w = pkh2(r0.w, r1.w);
    *(uint4*)(dst + (size_t)kp * cols + c4) = o;
}

#define NXI ((BATCH * NHID / 2) * (LEN / 4))   // 524288
#define NWI ((NHID / 2) * (DQKV / 4))          // 16384
#define NOI ((DQKV / 2) * (DOUT / 4))          // 131072
#define NTI (NXI + 3 * NWI + NOI)              // 704512

__global__ __launch_bounds__(256) void pack_all(
    const float* __restrict__ x,  const float* __restrict__ wq,
    const float* __restrict__ wk, const float* __restrict__ wv,
    const float* __restrict__ wo)
{
    int i = blockIdx.x * 256 + threadIdx.x;
    if (i >= NTI) return;
    if (i < NXI)                { pack_item(x,  g_xh,  LEN,  i); }
    else if (i < NXI + NWI)     { pack_item(wq, g_wqh, DQKV, i - NXI); }
    else if (i < NXI + 2 * NWI) { pack_item(wk, g_wkh, DQKV, i - NXI - NWI); }
    else if (i < NXI + 3 * NWI) { pack_item(wv, g_wvh, DQKV, i - NXI - 2 * NWI); }
    else                        { pack_item(wo, g_woh, DOUT, i - NXI - 3 * NWI); }
}

// 3-buffer / 2-sync mainloop (chunk cc+2 issued before waiting for cc)
#define PIPE3(ISSUE_MACRO, NCH, ABASE, BBASE)                                 \
    ISSUE_MACRO(0, 0);                                                        \
    ISSUE_MACRO(1, BKP);                                                      \
    for (int cc = 0; cc < (NCH); cc++) {                                      \
        const int cur = cc % 3;                                               \
        if (cc + 2 < (NCH)) { ISSUE_MACRO((cc + 2) % 3, (cc + 2) * BKP);      \
                              CP_WAIT(2); }                                   \
        else if (cc + 1 < (NCH)) { CP_WAIT(1); }                              \
        else { CP_WAIT(0); }                                                  \
        __syncthreads();                                                      \
        mma_chunk64((ABASE) + cur * OBSZ, (BBASE) + cur * OBSZ,               \
                    acc, mw, nw, c, g);                                       \
        __syncthreads();                                                      \
    }

// ---------------- Kernel 1: QKV projection ----------------
__global__ __launch_bounds__(128, 2) void qkv_mma(
    const float* __restrict__ bq, const float* __restrict__ bk,
    const float* __restrict__ bv)
{
    extern __shared__ uint32_t sm[];
    const int tid = threadIdx.x, lane = tid & 31, wid = tid >> 5;
    const int c = lane & 3, g = lane >> 2;
    const int mw = (wid & 1) * 64, nw = (wid >> 1) * 64;

    const int m0 = blockIdx.x * 128;
    const int bb = m0 >> 11;
    const int l0 = m0 & (LEN - 1);
    const int yy = blockIdx.y;               // 0..11
    const int mat = yy >> 2;
    const int n0 = (yy & 3) * 128;

    const uint32_t* W = (mat == 0) ? g_wqh : (mat == 1) ? g_wkh : g_wvh;
    const float* bias = (mat == 0) ? bq : (mat == 1) ? bk : bv;

    const uint32_t sbase = smem_u32(sm);
    const int kk0 = tid >> 5, m4s = (tid & 31) * 4;
    const uint32_t sdst = (uint32_t)(kk0 * POB + m4s) * 4;
    const uint32_t* aS = g_xh + ((size_t)bb * 128 + kk0) * LEN + l0 + m4s;
    const uint32_t* bS = W + (size_t)kk0 * DQKV + n0 + m4s;

    uint32_t aA[3], bA[3];
#pragma unroll
    for (int i = 0; i < 3; i++) {
        aA[i] = sbase + i * OBSZ * 4;
        bA[i] = sbase + (3 + i) * OBSZ * 4;
    }

#define Q_ISSUE(buf, k0p)                                                     \
    {                                                                         \
        _Pragma("unroll") for (int j = 0; j < 4; j++) {                       \
            cpa16(aA[buf] + sdst + j * (4 * POB * 4),                         \
                  aS + (size_t)((k0p) + 4 * j) * LEN);                        \
            cpa16(bA[buf] + sdst + j * (4 * POB * 4),                         \
                  bS + (size_t)((k0p) + 4 * j) * DQKV);                       \
        }                                                                     \
        CP_COMMIT();                                                          \
    }

    float acc[4][8][4];
#pragma unroll
    for (int i = 0; i < 4; i++)
#pragma unroll
        for (int j = 0; j < 8; j++)
#pragma unroll
            for (int r = 0; r < 4; r++) acc[i][j][r] = 0.f;

    PIPE3(Q_ISSUE, (NHID / 2) / BKP, sm, sm + 3 * OBSZ);   // 8 chunks
#undef Q_ISSUE

    // Epilogue: bias + pack to fp16 d-pair words -> g_qkvh
#pragma unroll
    for (int fm = 0; fm < 4; fm++)
#pragma unroll
        for (int fn = 0; fn < 8; fn++) {
            int m = m0 + mw + fm * 16 + g;
            int n = nw + fn * 8 + c * 2;
            float bx = __ldg(bias + n0 + n), by = __ldg(bias + n0 + n + 1);
            uint32_t* p = g_qkvh + (size_t)m * 768 + mat * 256 + ((n0 + n) >> 1);
            p[0]               = pkh2(acc[fm][fn][0] + bx, acc[fm][fn][1] + by);
            p[(size_t)8 * 768] = pkh2(acc[fm][fn][2] + bx, acc[fm][fn][3] + by);
        }
}

// ---------------- Kernel 2: window-3 attention (unchanged) ----------------
__global__ __launch_bounds__(256) void attn_t()
{
    __shared__ float att_s[32 * 66];   // [li][d] pitch 66
    const int tid = threadIdx.x, warp = tid >> 5, lane = tid & 31;
    const int bid = blockIdx.x;
    const int b = bid >> 9;
    const int head = (bid >> 6) & 7;
    const int l0 = (bid & 63) * 32;

#pragma unroll
    for (int i = 0; i < 4; i++) {
        const int li = warp * 4 + i;
        const int l = l0 + li;
        const size_t mrow = (size_t)b * LEN + l;
        const uint32_t* base = g_qkvh + mrow * 768 + head * 32 + lane;
        const float2 qv = uph2(base[0]);

        float  s[3];
        float2 vv[3];
#pragma unroll
        for (int w = 0; w < 3; w++) {
            int lw = l + w - 1;
            bool ok = (unsigned)lw < (unsigned)LEN;
            float2 kv = make_float2(0.f, 0.f);
            vv[w] = make_float2(0.f, 0.f);
            if (ok) {
                const uint32_t* pw = base + (intptr_t)(w - 1) * 768;
                kv    = uph2(pw[256]);
                vv[w] = uph2(pw[512]);
            }
            float p = qv.x * kv.x + qv.y * kv.y;
            p += __shfl_xor_sync(0xffffffffu, p, 16);
            p += __shfl_xor_sync(0xffffffffu, p, 8);
            p += __shfl_xor_sync(0xffffffffu, p, 4);
            p += __shfl_xor_sync(0xffffffffu, p, 2);
            p += __shfl_xor_sync(0xffffffffu, p, 1);
            s[w] = p * 0.125f;
        }

        float mx = fmaxf(s[0], fmaxf(s[1], s[2]));
        float e0 = expf(s[0] - mx), e1 = expf(s[1] - mx), e2 = expf(s[2] - mx);
        float inv = 1.0f / (e0 + e1 + e2);
        float ax = (e0 * vv[0].x + e1 * vv[1].x + e2 * vv[2].x) * inv;
        float ay = (e0 * vv[0].y + e1 * vv[1].y + e2 * vv[2].y) * inv;
        *(float2*)&att_s[li * 66 + lane * 2] = make_float2(ax, ay);
    }
    __syncthreads();

    {
        int dp = tid >> 3;              // 0..31
        int l4 = (tid & 7) * 4;         // 0..28
        uint4 v;
        v.x = pkh2(att_s[(l4 + 0) * 66 + 2 * dp], att_s[(l4 + 0) * 66 + 2 * dp + 1]);
        v.y = pkh2(att_s[(l4 + 1) * 66 + 2 * dp], att_s[(l4 + 1) * 66 + 2 * dp + 1]);
        v.z = pkh2(att_s[(l4 + 2) * 66 + 2 * dp], att_s[(l4 + 2) * 66 + 2 * dp + 1]);
        v.w = pkh2(att_s[(l4 + 3) * 66 + 2 * dp], att_s[(l4 + 3) * 66 + 2 * dp + 1]);
        *(uint4*)(g_atth + (size_t)(head * 32 + dp) * MTOT
                  + (size_t)b * LEN + l0 + l4) = v;
    }
}

// ---------------- Kernel 3: output projection ----------------
__global__ __launch_bounds__(128, 2) void out_mma(
    const float* __restrict__ bo, float* __restrict__ out)
{
    extern __shared__ uint32_t sm[];
    const int tid = threadIdx.x, lane = tid & 31, wid = tid >> 5;
    const int c = lane & 3, g = lane >> 2;
    const int mw = (wid & 1) * 64, nw = (wid >> 1) * 64;

    const int m0 = blockIdx.x * 128;
    const int bb = m0 >> 11;
    const int l0 = m0 & (LEN - 1);
    const int n0 = blockIdx.y * 128;

    const uint32_t sbase = smem_u32(sm);
    const int kk0 = tid >> 5, m4s = (tid & 31) * 4;
    const uint32_t sdst = (uint32_t)(kk0 * POB + m4s) * 4;
    const uint32_t* aS = g_atth + m0 + (size_t)kk0 * MTOT + m4s;
    const uint32_t* bS = g_woh + n0 + (size_t)kk0 * DOUT + m4s;

    uint32_t aA[3], bA[3];
#pragma unroll
    for (int i = 0; i < 3; i++) {
        aA[i] = sbase + i * OBSZ * 4;
        bA[i] = sbase + (3 + i) * OBSZ * 4;
    }

#define O_ISSUE(buf, k0p)                                                     \
    {                                                                         \
        _Pragma("unroll") for (int j = 0; j < 4; j++) {                       \
            cpa16(aA[buf] + sdst + j * (4 * POB * 4),                         \
                  aS + (size_t)((k0p) + 4 * j) * MTOT);                       \
            cpa16(bA[buf] + sdst + j * (4 * POB * 4),                         \
                  bS + (size_t)((k0p) + 4 * j) * DOUT);                       \
        }                                                                     \
        CP_COMMIT();                                                          \
    }

    float acc[4][8][4];
#pragma unroll
    for (int i = 0; i < 4; i++)
#pragma unroll
        for (int j = 0; j < 8; j++)
#pragma unroll
            for (int r = 0; r < 4; r++) acc[i][j][r] = 0.f;

    PIPE3(O_ISSUE, (DQKV / 2) / BKP, sm, sm + 3 * OBSZ);   // 16 chunks
#undef O_ISSUE

    // Epilogue: two 64-n halves through smem bounce [n][m] (fp32, pitch 132)
    float* ep = (float*)sm;   // 64*132*4 = 33792 B <= SMEM_G3
#pragma unroll
    for (int h = 0; h < 2; h++) {
        if ((nw >> 6) == h) {
#pragma unroll
            for (int fm = 0; fm < 4; fm++)
#pragma unroll
                for (int fn = 0; fn < 8; fn++) {
                    int nrel = fn * 8 + c * 2;
                    int mrel = mw + fm * 16 + g;
                    ep[nrel * EPPO + mrel]           = acc[fm][fn][0];
                    ep[(nrel + 1) * EPPO + mrel]     = acc[fm][fn][1];
                    ep[nrel * EPPO + mrel + 8]       = acc[fm][fn][2];
                    ep[(nrel + 1) * EPPO + mrel + 8] = acc[fm][fn][3];
                }
        }
        __syncthreads();
#pragma unroll
        for (int i = 0; i < 16; i++) {
            int f = tid + i * 128;
            int nr = f >> 5;
            int m4 = (f & 31) * 4;
            float4 v = *(float4*)&ep[nr * EPPO + m4];
            float bj = __ldg(bo + n0 + h * 64 + nr);
            v.x += bj; v.y += bj; v.z += bj; v.w += bj;
            *(float4*)(out + ((size_t)(bb * DOUT + n0 + h * 64 + nr)) * LEN
                       + l0 + m4) = v;
        }
        __syncthreads();
    }
}

// ---------------- launch ----------------
extern "C" void kernel_launch(void* const* d_in, const int* in_sizes, int n_in,
                              void* d_out, int out_size)
{
    const float* x  = (const float*)d_in[0];
    const float* Wq = (const float*)d_in[1];
    const float* bq = (const float*)d_in[2];
    const float* Wk = (const float*)d_in[3];
    const float* bk = (const float*)d_in[4];
    const float* Wv = (const float*)d_in[5];
    const float* bv = (const float*)d_in[6];
    const float* Wo = (const float*)d_in[7];
    const float* bo = (const float*)d_in[8];
    float* out = (float*)d_out;

    cudaFuncSetAttribute(qkv_mma, cudaFuncAttributeMaxDynamicSharedMemorySize, SMEM_G3);
    cudaFuncSetAttribute(out_mma, cudaFuncAttributeMaxDynamicSharedMemorySize, SMEM_G3);

    pack_all<<<(NTI + 255) / 256, 256>>>(x, Wq, Wk, Wv, Wo);
    qkv_mma<<<dim3(MTOT / 128, 12), 128, SMEM_G3>>>(bq, bk, bv);
    attn_t<<<BATCH * NHEAD * (LEN / 32), 256>>>();
    out_mma<<<dim3(MTOT / 128, DOUT / 128), 128, SMEM_G3>>>(bo, out);
}

// round 16
// speedup vs baseline: 1.0472x; 1.0472x over previous
#include <cuda_runtime.h>
#include <cuda_fp16.h>
#include <cstdint>

// ---------------- problem constants ----------------
#define BATCH 8
#define NHID 256
#define LEN 2048
#define NHEAD 8
#define HDIM 64
#define DQKV 512
#define DOUT 2048
#define MTOT (BATCH * LEN)   // 16384

// ---------------- GEMM tiling (128x128 CTA, 64x64 warp, 128 thr) ----------------
#define BKP 16                // kp rows per chunk (= 32 k elements)
#define POB 136               // smem pitch (uint32)
#define OBSZ (BKP * POB)      // 2176 uint32 per buffer
#define EPPO 132              // out epilogue bounce pitch
#define SMEM_G (4 * OBSZ * 4)   // 34816 B (A0,A1,B0,B1); out epi half = 33792 B

// Scratch (allocation-free). Operands packed as half2 k-pairs: word[kp][col].
__device__ uint32_t g_xh[(size_t)(BATCH * NHID / 2) * LEN];   // [1024][2048]
__device__ uint32_t g_wqh[(NHID / 2) * DQKV];
__device__ uint32_t g_wkh[(NHID / 2) * DQKV];
__device__ uint32_t g_wvh[(NHID / 2) * DQKV];
__device__ uint32_t g_woh[(DQKV / 2) * DOUT];                 // [256][2048]
__device__ uint32_t g_qkvh[(size_t)MTOT * 768];               // fp16 q/k/v, d-pair words
__device__ uint32_t g_atth[(size_t)(DQKV / 2) * MTOT];        // [256][16384]

// ---------------- helpers ----------------
__device__ __forceinline__ uint32_t pkh2(float a, float b) {
    __half2 h = __floats2half2_rn(a, b);
    return *reinterpret_cast<uint32_t*>(&h);
}
__device__ __forceinline__ float2 uph2(uint32_t u) {
    __half2 h;
    *reinterpret_cast<uint32_t*>(&h) = u;
    return __half22float2(h);
}
__device__ __forceinline__ uint32_t smem_u32(const void* p) {
    uint32_t a;
    asm("{ .reg .u64 t; cvta.to.shared.u64 t, %1; cvt.u32.u64 %0, t; }" : "=r"(a) : "l"(p));
    return a;
}
__device__ __forceinline__ void cpa16(uint32_t dst, const void* src) {
    asm volatile("cp.async.cg.shared.global [%0], [%1], 16;" :: "r"(dst), "l"(src));
}
#define CP_COMMIT() asm volatile("cp.async.commit_group;" ::: "memory")
#define CP_WAIT(n)  asm volatile("cp.async.wait_group %0;" :: "n"(n) : "memory")

__device__ __forceinline__ void mma16(float& d0, float& d1, float& d2, float& d3,
                                      uint32_t a0, uint32_t a1, uint32_t a2, uint32_t a3,
                                      uint32_t b0, uint32_t b1) {
    asm volatile(
        "mma.sync.aligned.m16n8k16.row.col.f32.f16.f16.f32 "
        "{%0,%1,%2,%3}, {%4,%5,%6,%7}, {%8,%9}, {%0,%1,%2,%3};"
        : "+f"(d0), "+f"(d1), "+f"(d2), "+f"(d3)
        : "r"(a0), "r"(a1), "r"(a2), "r"(a3), "r"(b0), "r"(b1));
}

// ---- 64x64 warp-tile chunk (2 k16-steps = 16 kp) ----
__device__ __forceinline__ void mma_chunk64(const uint32_t* __restrict__ Ab,
                                            const uint32_t* __restrict__ Bb,
                                            float acc[4][8][4], int mw, int nw,
                                            int c, int g) {
#pragma unroll
    for (int ks = 0; ks < 2; ks++) {
        const int kb = ks * 8;
        uint32_t a[4][4];
#pragma unroll
        for (int fm = 0; fm < 4; fm++) {
            const uint32_t* p = Ab + (kb + c) * POB + mw + fm * 16 + g;
            a[fm][0] = p[0];
            a[fm][1] = p[8];
            a[fm][2] = p[4 * POB];
            a[fm][3] = p[4 * POB + 8];
        }
#pragma unroll
        for (int fn = 0; fn < 8; fn++) {
            const uint32_t* q = Bb + (kb + c) * POB + nw + fn * 8 + g;
            uint32_t b0 = q[0];
            uint32_t b1 = q[4 * POB];
#pragma unroll
            for (int fm = 0; fm < 4; fm++)
                mma16(acc[fm][fn][0], acc[fm][fn][1], acc[fm][fn][2], acc[fm][fn][3],
                      a[fm][0], a[fm][1], a[fm][2], a[fm][3], b0, b1);
        }
    }
}

// ---------------- prep: pack fp32 [K][N] -> half2-k-pair words [K/2][N] ----------------
__device__ __forceinline__ void pack_item(const float* __restrict__ src,
                                          uint32_t* __restrict__ dst,
                                          int cols, int i) {
    int kp = i / (cols / 4);
    int c4 = (i % (cols / 4)) * 4;
    const float4 r0 = *(const float4*)(src + (size_t)(2 * kp) * cols + c4);
    const float4 r1 = *(const float4*)(src + (size_t)(2 * kp + 1) * cols + c4);
    uint4 o;
    o.x = pkh2(r0.x, r1.x);
    o.y = pkh2(r0.y, r1.y);
    o.z = pkh2(r0.z, r1.z);
    o.w = pkh2(r0.w, r1.w);
    *(uint4*)(dst + (size_t)kp * cols + c4) = o;
}

#define NXI ((BATCH * NHID / 2) * (LEN / 4))   // 524288
#define NWI ((NHID / 2) * (DQKV / 4))          // 16384
#define NOI ((DQKV / 2) * (DOUT / 4))          // 131072
#define NTI (NXI + 3 * NWI + NOI)              // 704512

__global__ __launch_bounds__(256) void pack_all(
    const float* __restrict__ x,  const float* __restrict__ wq,
    const float* __restrict__ wk, const float* __restrict__ wv,
    const float* __restrict__ wo)
{
    int i = blockIdx.x * 256 + threadIdx.x;
    if (i >= NTI) return;
    if (i < NXI)                { pack_item(x,  g_xh,  LEN,  i); }
    else if (i < NXI + NWI)     { pack_item(wq, g_wqh, DQKV, i - NXI); }
    else if (i < NXI + 2 * NWI) { pack_item(wk, g_wkh, DQKV, i - NXI - NWI); }
    else if (i < NXI + 3 * NWI) { pack_item(wv, g_wvh, DQKV, i - NXI - 2 * NWI); }
    else                        { pack_item(wo, g_woh, DOUT, i - NXI - 3 * NWI); }
}

// ---------------- Kernel 1: QKV projection (exact R13) ----------------
__global__ __launch_bounds__(128, 2) void qkv_mma(
    const float* __restrict__ bq, const float* __restrict__ bk,
    const float* __restrict__ bv)
{
    extern __shared__ uint32_t sm[];
    const int tid = threadIdx.x, lane = tid & 31, wid = tid >> 5;
    const int c = lane & 3, g = lane >> 2;
    const int mw = (wid & 1) * 64, nw = (wid >> 1) * 64;

    const int m0 = blockIdx.x * 128;
    const int bb = m0 >> 11;
    const int l0 = m0 & (LEN - 1);
    const int yy = blockIdx.y;               // 0..11
    const int mat = yy >> 2;
    const int n0 = (yy & 3) * 128;

    const uint32_t* W = (mat == 0) ? g_wqh : (mat == 1) ? g_wkh : g_wvh;
    const float* bias = (mat == 0) ? bq : (mat == 1) ? bk : bv;

    const uint32_t sbase = smem_u32(sm);
    const int kk0 = tid >> 5, m4s = (tid & 31) * 4;
    const uint32_t sdst = (uint32_t)(kk0 * POB + m4s) * 4;
    const uint32_t* aS = g_xh + ((size_t)bb * 128 + kk0) * LEN + l0 + m4s;
    const uint32_t* bS = W + (size_t)kk0 * DQKV + n0 + m4s;

    const uint32_t aA[2] = {sbase, sbase + OBSZ * 4};
    const uint32_t bA[2] = {sbase + 2 * OBSZ * 4, sbase + 3 * OBSZ * 4};

#define Q_ISSUE(buf, k0p)                                                     \
    {                                                                         \
        _Pragma("unroll") for (int j = 0; j < 4; j++) {                       \
            cpa16(aA[buf] + sdst + j * (4 * POB * 4),                         \
                  aS + (size_t)((k0p) + 4 * j) * LEN);                        \
            cpa16(bA[buf] + sdst + j * (4 * POB * 4),                         \
                  bS + (size_t)((k0p) + 4 * j) * DQKV);                       \
        }                                                                     \
        CP_COMMIT();                                                          \
    }

    float acc[4][8][4];
#pragma unroll
    for (int i = 0; i < 4; i++)
#pragma unroll
        for (int j = 0; j < 8; j++)
#pragma unroll
            for (int r = 0; r < 4; r++) acc[i][j][r] = 0.f;

    const int NCH = (NHID / 2) / BKP;   // 8 chunks
    Q_ISSUE(0, 0);
    for (int cc = 0; cc < NCH; cc++) {
        const int cur = cc & 1;
        if (cc + 1 < NCH) { Q_ISSUE(cur ^ 1, (cc + 1) * BKP); CP_WAIT(1); }
        else              { CP_WAIT(0); }
        __syncthreads();
        mma_chunk64(sm + cur * OBSZ, sm + (2 + cur) * OBSZ, acc, mw, nw, c, g);
        __syncthreads();
    }
#undef Q_ISSUE

    // Epilogue: bias + pack to fp16 d-pair words -> g_qkvh
#pragma unroll
    for (int fm = 0; fm < 4; fm++)
#pragma unroll
        for (int fn = 0; fn < 8; fn++) {
            int m = m0 + mw + fm * 16 + g;
            int n = nw + fn * 8 + c * 2;
            float bx = __ldg(bias + n0 + n), by = __ldg(bias + n0 + n + 1);
            uint32_t* p = g_qkvh + (size_t)m * 768 + mat * 256 + ((n0 + n) >> 1);
            p[0]               = pkh2(acc[fm][fn][0] + bx, acc[fm][fn][1] + by);
            p[(size_t)8 * 768] = pkh2(acc[fm][fn][2] + bx, acc[fm][fn][3] + by);
        }
}

// ---------------- Kernel 2: window-3 attention — smem-cached k/v ----------------
__global__ __launch_bounds__(256) void attn_t()
{
    __shared__ uint32_t k_s[34 * 32];   // rows l0-1 .. l0+32, zero-padded
    __shared__ uint32_t v_s[34 * 32];
    __shared__ float att_s[32 * 66];    // [li][d] pitch 66
    const int tid = threadIdx.x, warp = tid >> 5, lane = tid & 31;
    const int bid = blockIdx.x;
    const int b = bid >> 9;
    const int head = (bid >> 6) & 7;
    const int l0 = (bid & 63) * 32;

    // Stage k/v rows l0-1 .. l0+32 once (3x traffic reduction vs per-l loads)
    for (int idx = tid; idx < 34 * 32; idx += 256) {
        int r = idx >> 5, col = idx & 31;
        int l = l0 - 1 + r;
        uint32_t kw = 0u, vw = 0u;
        if ((unsigned)l < (unsigned)LEN) {
            const uint32_t* p = g_qkvh + ((size_t)b * LEN + l) * 768 + head * 32 + col;
            kw = p[256];
            vw = p[512];
        }
        k_s[idx] = kw;
        v_s[idx] = vw;
    }
    __syncthreads();

#pragma unroll
    for (int i = 0; i < 4; i++) {
        const int li = warp * 4 + i;
        const int l = l0 + li;
        const float2 qv = uph2(g_qkvh[((size_t)b * LEN + l) * 768 + head * 32 + lane]);

        float  s[3];
        float2 vv[3];
#pragma unroll
        for (int w = 0; w < 3; w++) {
            const int r = li + w;            // smem row for l + w - 1
            const float2 kv = uph2(k_s[r * 32 + lane]);
            vv[w] = uph2(v_s[r * 32 + lane]);
            float p = qv.x * kv.x + qv.y * kv.y;
            p += __shfl_xor_sync(0xffffffffu, p, 16);
            p += __shfl_xor_sync(0xffffffffu, p, 8);
            p += __shfl_xor_sync(0xffffffffu, p, 4);
            p += __shfl_xor_sync(0xffffffffu, p, 2);
            p += __shfl_xor_sync(0xffffffffu, p, 1);
            s[w] = p * 0.125f;               // 1/sqrt(64)
        }

        float mx = fmaxf(s[0], fmaxf(s[1], s[2]));
        float e0 = expf(s[0] - mx), e1 = expf(s[1] - mx), e2 = expf(s[2] - mx);
        float inv = 1.0f / (e0 + e1 + e2);
        float ax = (e0 * vv[0].x + e1 * vv[1].x + e2 * vv[2].x) * inv;
        float ay = (e0 * vv[0].y + e1 * vv[1].y + e2 * vv[2].y) * inv;
        *(float2*)&att_s[li * 66 + lane * 2] = make_float2(ax, ay);
    }
    __syncthreads();

    // write g_atth[(head*32+dp)][b*2048 + l0 + l], 4 l's per thread (16B store)
    {
        int dp = tid >> 3;              // 0..31
        int l4 = (tid & 7) * 4;         // 0..28
        uint4 v;
        v.x = pkh2(att_s[(l4 + 0) * 66 + 2 * dp], att_s[(l4 + 0) * 66 + 2 * dp + 1]);
        v.y = pkh2(att_s[(l4 + 1) * 66 + 2 * dp], att_s[(l4 + 1) * 66 + 2 * dp + 1]);
        v.z = pkh2(att_s[(l4 + 2) * 66 + 2 * dp], att_s[(l4 + 2) * 66 + 2 * dp + 1]);
        v.w = pkh2(att_s[(l4 + 3) * 66 + 2 * dp], att_s[(l4 + 3) * 66 + 2 * dp + 1]);
        *(uint4*)(g_atth + (size_t)(head * 32 + dp) * MTOT
                  + (size_t)b * LEN + l0 + l4) = v;
    }
}

// ---------------- Kernel 3: output projection (exact R13) ----------------
__global__ __launch_bounds__(128, 2) void out_mma(
    const float* __restrict__ bo, float* __restrict__ out)
{
    extern __shared__ uint32_t sm[];
    const int tid = threadIdx.x, lane = tid & 31, wid = tid >> 5;
    const int c = lane & 3, g = lane >> 2;
    const int mw = (wid & 1) * 64, nw = (wid >> 1) * 64;

    const int m0 = blockIdx.x * 128;
    const int bb = m0 >> 11;
    const int l0 = m0 & (LEN - 1);
    const int n0 = blockIdx.y * 128;

    const uint32_t sbase = smem_u32(sm);
    const int kk0 = tid >> 5, m4s = (tid & 31) * 4;
    const uint32_t sdst = (uint32_t)(kk0 * POB + m4s) * 4;
    const uint32_t* aS = g_atth + m0 + (size_t)kk0 * MTOT + m4s;
    const uint32_t* bS = g_woh + n0 + (size_t)kk0 * DOUT + m4s;

    const uint32_t aA[2] = {sbase, sbase + OBSZ * 4};
    const uint32_t bA[2] = {sbase + 2 * OBSZ * 4, sbase + 3 * OBSZ * 4};

#define O_ISSUE(buf, k0p)                                                     \
    {                                                                         \
        _Pragma("unroll") for (int j = 0; j < 4; j++) {                       \
            cpa16(aA[buf] + sdst + j * (4 * POB * 4),                         \
                  aS + (size_t)((k0p) + 4 * j) * MTOT);                       \
            cpa16(bA[buf] + sdst + j * (4 * POB * 4),                         \
                  bS + (size_t)((k0p) + 4 * j) * DOUT);                       \
        }                                                                     \
        CP_COMMIT();                                                          \
    }

    float acc[4][8][4];
#pragma unroll
    for (int i = 0; i < 4; i++)
#pragma unroll
        for (int j = 0; j < 8; j++)
#pragma unroll
            for (int r = 0; r < 4; r++) acc[i][j][r] = 0.f;

    const int NCH = (DQKV / 2) / BKP;   // 16 chunks
    O_ISSUE(0, 0);
    for (int cc = 0; cc < NCH; cc++) {
        const int cur = cc & 1;
        if (cc + 1 < NCH) { O_ISSUE(cur ^ 1, (cc + 1) * BKP); CP_WAIT(1); }
        else              { CP_WAIT(0); }
        __syncthreads();
        mma_chunk64(sm + cur * OBSZ, sm + (2 + cur) * OBSZ, acc, mw, nw, c, g);
        __syncthreads();
    }
#undef O_ISSUE

    // Epilogue: two 64-n halves through smem bounce [n][m] (fp32, pitch 132)
    float* ep = (float*)sm;   // 64*132*4 = 33792 B <= SMEM_G
#pragma unroll
    for (int h = 0; h < 2; h++) {
        if ((nw >> 6) == h) {
#pragma unroll
            for (int fm = 0; fm < 4; fm++)
#pragma unroll
                for (int fn = 0; fn < 8; fn++) {
                    int nrel = fn * 8 + c * 2;
                    int mrel = mw + fm * 16 + g;
                    ep[nrel * EPPO + mrel]           = acc[fm][fn][0];
                    ep[(nrel + 1) * EPPO + mrel]     = acc[fm][fn][1];
                    ep[nrel * EPPO + mrel + 8]       = acc[fm][fn][2];
                    ep[(nrel + 1) * EPPO + mrel + 8] = acc[fm][fn][3];
                }
        }
        __syncthreads();
#pragma unroll
        for (int i = 0; i < 16; i++) {
            int f = tid + i * 128;
            int nr = f >> 5;
            int m4 = (f & 31) * 4;
            float4 v = *(float4*)&ep[nr * EPPO + m4];
            float bj = __ldg(bo + n0 + h * 64 + nr);
            v.x += bj; v.y += bj; v.z += bj; v.w += bj;
            *(float4*)(out + ((size_t)(bb * DOUT + n0 + h * 64 + nr)) * LEN
                       + l0 + m4) = v;
        }
        __syncthreads();
    }
}

// ---------------- launch ----------------
extern "C" void kernel_launch(void* const* d_in, const int* in_sizes, int n_in,
                              void* d_out, int out_size)
{
    const float* x  = (const float*)d_in[0];
    const float* Wq = (const float*)d_in[1];
    const float* bq = (const float*)d_in[2];
    const float* Wk = (const float*)d_in[3];
    const float* bk = (const float*)d_in[4];
    const float* Wv = (const float*)d_in[5];
    const float* bv = (const float*)d_in[6];
    const float* Wo = (const float*)d_in[7];
    const float* bo = (const float*)d_in[8];
    float* out = (float*)d_out;

    cudaFuncSetAttribute(qkv_mma, cudaFuncAttributeMaxDynamicSharedMemorySize, SMEM_G);
    cudaFuncSetAttribute(out_mma, cudaFuncAttributeMaxDynamicSharedMemorySize, SMEM_G);

    pack_all<<<(NTI + 255) / 256, 256>>>(x, Wq, Wk, Wv, Wo);
    qkv_mma<<<dim3(MTOT / 128, 12), 128, SMEM_G>>>(bq, bk, bv);
    attn_t<<<BATCH * NHEAD * (LEN / 32), 256>>>();
    out_mma<<<dim3(MTOT / 128, DOUT / 128), 128, SMEM_G>>>(bo, out);
}

// round 17
// speedup vs baseline: 1.0705x; 1.0222x over previous
#include <cuda_runtime.h>
#include <cuda_fp16.h>
#include <cstdint>

// ---------------- problem constants ----------------
#define BATCH 8
#define NHID 256
#define LEN 2048
#define NHEAD 8
#define HDIM 64
#define DQKV 512
#define DOUT 2048
#define MTOT (BATCH * LEN)   // 16384

// ---------------- GEMM tiling (128x128 CTA, 64x64 warp, 128 thr) ----------------
#define BKP 16                // kp rows per chunk (= 32 k elements)
#define POB 136               // smem pitch (uint32)
#define OBSZ (BKP * POB)      // 2176 uint32 per buffer
#define EPPO 132              // out epilogue bounce pitch
#define SMEM_G (4 * OBSZ * 4)   // 34816 B (A0,A1,B0,B1); out epi half = 33792 B

// Scratch (allocation-free). Operands packed as half2 k-pairs: word[kp][col].
__device__ uint32_t g_xh[(size_t)(BATCH * NHID / 2) * LEN];   // [1024][2048]
__device__ uint32_t g_wqh[(NHID / 2) * DQKV];
__device__ uint32_t g_wkh[(NHID / 2) * DQKV];
__device__ uint32_t g_wvh[(NHID / 2) * DQKV];
__device__ uint32_t g_woh[(DQKV / 2) * DOUT];                 // [256][2048]
__device__ uint32_t g_qkvh[(size_t)MTOT * 768];               // fp16 q/k/v, d-pair words
__device__ uint32_t g_atth[(size_t)(DQKV / 2) * MTOT];        // [256][16384]

// ---------------- helpers ----------------
__device__ __forceinline__ uint32_t pkh2(float a, float b) {
    __half2 h = __floats2half2_rn(a, b);
    return *reinterpret_cast<uint32_t*>(&h);
}
__device__ __forceinline__ float2 uph2(uint32_t u) {
    __half2 h;
    *reinterpret_cast<uint32_t*>(&h) = u;
    return __half22float2(h);
}
__device__ __forceinline__ uint32_t smem_u32(const void* p) {
    uint32_t a;
    asm("{ .reg .u64 t; cvta.to.shared.u64 t, %1; cvt.u32.u64 %0, t; }" : "=r"(a) : "l"(p));
    return a;
}
__device__ __forceinline__ void cpa16(uint32_t dst, const void* src) {
    asm volatile("cp.async.cg.shared.global [%0], [%1], 16;" :: "r"(dst), "l"(src));
}
#define CP_COMMIT() asm volatile("cp.async.commit_group;" ::: "memory")
#define CP_WAIT(n)  asm volatile("cp.async.wait_group %0;" :: "n"(n) : "memory")

__device__ __forceinline__ void mma16(float& d0, float& d1, float& d2, float& d3,
                                      uint32_t a0, uint32_t a1, uint32_t a2, uint32_t a3,
                                      uint32_t b0, uint32_t b1) {
    asm volatile(
        "mma.sync.aligned.m16n8k16.row.col.f32.f16.f16.f32 "
        "{%0,%1,%2,%3}, {%4,%5,%6,%7}, {%8,%9}, {%0,%1,%2,%3};"
        : "+f"(d0), "+f"(d1), "+f"(d2), "+f"(d3)
        : "r"(a0), "r"(a1), "r"(a2), "r"(a3), "r"(b0), "r"(b1));
}

// ---- 64x64 warp-tile chunk (2 k16-steps = 16 kp) ----
__device__ __forceinline__ void mma_chunk64(const uint32_t* __restrict__ Ab,
                                            const uint32_t* __restrict__ Bb,
                                            float acc[4][8][4], int mw, int nw,
                                            int c, int g) {
#pragma unroll
    for (int ks = 0; ks < 2; ks++) {
        const int kb = ks * 8;
        uint32_t a[4][4];
#pragma unroll
        for (int fm = 0; fm < 4; fm++) {
            const uint32_t* p = Ab + (kb + c) * POB + mw + fm * 16 + g;
            a[fm][0] = p[0];
            a[fm][1] = p[8];
            a[fm][2] = p[4 * POB];
            a[fm][3] = p[4 * POB + 8];
        }
#pragma unroll
        for (int fn = 0; fn < 8; fn++) {
            const uint32_t* q = Bb + (kb + c) * POB + nw + fn * 8 + g;
            uint32_t b0 = q[0];
            uint32_t b1 = q[4 * POB];
#pragma unroll
            for (int fm = 0; fm < 4; fm++)
                mma16(acc[fm][fn][0], acc[fm][fn][1], acc[fm][fn][2], acc[fm][fn][3],
                      a[fm][0], a[fm][1], a[fm][2], a[fm][3], b0, b1);
        }
    }
}

// ---------------- prep: pack fp32 [K][N] -> half2-k-pair words [K/2][N] ----------------
__device__ __forceinline__ void pack_item(const float* __restrict__ src,
                                          uint32_t* __restrict__ dst,
                                          int cols, int i) {
    int kp = i / (cols / 4);
    int c4 = (i % (cols / 4)) * 4;
    const float4 r0 = *(const float4*)(src + (size_t)(2 * kp) * cols + c4);
    const float4 r1 = *(const float4*)(src + (size_t)(2 * kp + 1) * cols + c4);
    uint4 o;
    o.x = pkh2(r0.x, r1.x);
    o.y = pkh2(r0.y, r1.y);
    o.z = pkh2(r0.z, r1.z);
    o.w = pkh2(r0.w, r1.w);
    *(uint4*)(dst + (size_t)kp * cols + c4) = o;
}

#define NXI ((BATCH * NHID / 2) * (LEN / 4))   // 524288
#define NWI ((NHID / 2) * (DQKV / 4))          // 16384
#define NOI ((DQKV / 2) * (DOUT / 4))          // 131072
#define NTI (NXI + 3 * NWI + NOI)              // 704512

__global__ __launch_bounds__(256) void pack_all(
    const float* __restrict__ x,  const float* __restrict__ wq,
    const float* __restrict__ wk, const float* __restrict__ wv,
    const float* __restrict__ wo)
{
    int i = blockIdx.x * 256 + threadIdx.x;
    if (i >= NTI) return;
    if (i < NXI)                { pack_item(x,  g_xh,  LEN,  i); }
    else if (i < NXI + NWI)     { pack_item(wq, g_wqh, DQKV, i - NXI); }
    else if (i < NXI + 2 * NWI) { pack_item(wk, g_wkh, DQKV, i - NXI - NWI); }
    else if (i < NXI + 3 * NWI) { pack_item(wv, g_wvh, DQKV, i - NXI - 2 * NWI); }
    else                        { pack_item(wo, g_woh, DOUT, i - NXI - 3 * NWI); }
}

// ---------------- Kernel 1: QKV projection (exact R13) ----------------
__global__ __launch_bounds__(128, 2) void qkv_mma(
    const float* __restrict__ bq, const float* __restrict__ bk,
    const float* __restrict__ bv)
{
    extern __shared__ uint32_t sm[];
    const int tid = threadIdx.x, lane = tid & 31, wid = tid >> 5;
    const int c = lane & 3, g = lane >> 2;
    const int mw = (wid & 1) * 64, nw = (wid >> 1) * 64;

    const int m0 = blockIdx.x * 128;
    const int bb = m0 >> 11;
    const int l0 = m0 & (LEN - 1);
    const int yy = blockIdx.y;               // 0..11
    const int mat = yy >> 2;
    const int n0 = (yy & 3) * 128;

    const uint32_t* W = (mat == 0) ? g_wqh : (mat == 1) ? g_wkh : g_wvh;
    const float* bias = (mat == 0) ? bq : (mat == 1) ? bk : bv;

    const uint32_t sbase = smem_u32(sm);
    const int kk0 = tid >> 5, m4s = (tid & 31) * 4;
    const uint32_t sdst = (uint32_t)(kk0 * POB + m4s) * 4;
    const uint32_t* aS = g_xh + ((size_t)bb * 128 + kk0) * LEN + l0 + m4s;
    const uint32_t* bS = W + (size_t)kk0 * DQKV + n0 + m4s;

    const uint32_t aA[2] = {sbase, sbase + OBSZ * 4};
    const uint32_t bA[2] = {sbase + 2 * OBSZ * 4, sbase + 3 * OBSZ * 4};

#define Q_ISSUE(buf, k0p)                                                     \
    {                                                                         \
        _Pragma("unroll") for (int j = 0; j < 4; j++) {                       \
            cpa16(aA[buf] + sdst + j * (4 * POB * 4),                         \
                  aS + (size_t)((k0p) + 4 * j) * LEN);                        \
            cpa16(bA[buf] + sdst + j * (4 * POB * 4),                         \
                  bS + (size_t)((k0p) + 4 * j) * DQKV);                       \
        }                                                                     \
        CP_COMMIT();                                                          \
    }

    float acc[4][8][4];
#pragma unroll
    for (int i = 0; i < 4; i++)
#pragma unroll
        for (int j = 0; j < 8; j++)
#pragma unroll
            for (int r = 0; r < 4; r++) acc[i][j][r] = 0.f;

    const int NCH = (NHID / 2) / BKP;   // 8 chunks
    Q_ISSUE(0, 0);
    for (int cc = 0; cc < NCH; cc++) {
        const int cur = cc & 1;
        if (cc + 1 < NCH) { Q_ISSUE(cur ^ 1, (cc + 1) * BKP); CP_WAIT(1); }
        else              { CP_WAIT(0); }
        __syncthreads();
        mma_chunk64(sm + cur * OBSZ, sm + (2 + cur) * OBSZ, acc, mw, nw, c, g);
        __syncthreads();
    }
#undef Q_ISSUE

    // Epilogue: bias + pack to fp16 d-pair words -> g_qkvh
#pragma unroll
    for (int fm = 0; fm < 4; fm++)
#pragma unroll
        for (int fn = 0; fn < 8; fn++) {
            int m = m0 + mw + fm * 16 + g;
            int n = nw + fn * 8 + c * 2;
            float bx = __ldg(bias + n0 + n), by = __ldg(bias + n0 + n + 1);
            uint32_t* p = g_qkvh + (size_t)m * 768 + mat * 256 + ((n0 + n) >> 1);
            p[0]               = pkh2(acc[fm][fn][0] + bx, acc[fm][fn][1] + by);
            p[(size_t)8 * 768] = pkh2(acc[fm][fn][2] + bx, acc[fm][fn][3] + by);
        }
}

// ---------------- Kernel 2: window-3 attention (R13 structure, __expf) ----------------
__global__ __launch_bounds__(256) void attn_t()
{
    __shared__ float att_s[32 * 66];   // [li][d] pitch 66
    const int tid = threadIdx.x, warp = tid >> 5, lane = tid & 31;
    const int bid = blockIdx.x;
    const int b = bid >> 9;
    const int head = (bid >> 6) & 7;
    const int l0 = (bid & 63) * 32;

#pragma unroll
    for (int i = 0; i < 4; i++) {
        const int li = warp * 4 + i;
        const int l = l0 + li;
        const size_t mrow = (size_t)b * LEN + l;
        const uint32_t* base = g_qkvh + mrow * 768 + head * 32 + lane;
        const float2 qv = uph2(base[0]);

        float  s[3];
        float2 vv[3];
#pragma unroll
        for (int w = 0; w < 3; w++) {
            int lw = l + w - 1;
            bool ok = (unsigned)lw < (unsigned)LEN;
            float2 kv = make_float2(0.f, 0.f);
            vv[w] = make_float2(0.f, 0.f);
            if (ok) {
                const uint32_t* pw = base + (intptr_t)(w - 1) * 768;
                kv    = uph2(pw[256]);
                vv[w] = uph2(pw[512]);
            }
            float p = qv.x * kv.x + qv.y * kv.y;
            p += __shfl_xor_sync(0xffffffffu, p, 16);
            p += __shfl_xor_sync(0xffffffffu, p, 8);
            p += __shfl_xor_sync(0xffffffffu, p, 4);
            p += __shfl_xor_sync(0xffffffffu, p, 2);
            p += __shfl_xor_sync(0xffffffffu, p, 1);
            s[w] = p * 0.125f;   // 1/sqrt(64)
        }

        float mx = fmaxf(s[0], fmaxf(s[1], s[2]));
        float e0 = __expf(s[0] - mx), e1 = __expf(s[1] - mx), e2 = __expf(s[2] - mx);
        float inv = 1.0f / (e0 + e1 + e2);
        float ax = (e0 * vv[0].x + e1 * vv[1].x + e2 * vv[2].x) * inv;
        float ay = (e0 * vv[0].y + e1 * vv[1].y + e2 * vv[2].y) * inv;
        *(float2*)&att_s[li * 66 + lane * 2] = make_float2(ax, ay);
    }
    __syncthreads();

    // write g_atth[(head*32+dp)][b*2048 + l0 + l], 4 l's per thread (16B store)
    {
        int dp = tid >> 3;              // 0..31
        int l4 = (tid & 7) * 4;         // 0..28
        uint4 v;
        v.x = pkh2(att_s[(l4 + 0) * 66 + 2 * dp], att_s[(l4 + 0) * 66 + 2 * dp + 1]);
        v.y = pkh2(att_s[(l4 + 1) * 66 + 2 * dp], att_s[(l4 + 1) * 66 + 2 * dp + 1]);
        v.z = pkh2(att_s[(l4 + 2) * 66 + 2 * dp], att_s[(l4 + 2) * 66 + 2 * dp + 1]);
        v.w = pkh2(att_s[(l4 + 3) * 66 + 2 * dp], att_s[(l4 + 3) * 66 + 2 * dp + 1]);
        *(uint4*)(g_atth + (size_t)(head * 32 + dp) * MTOT
                  + (size_t)b * LEN + l0 + l4) = v;
    }
}

// ---------------- Kernel 3: output projection (exact R13) ----------------
__global__ __launch_bounds__(128, 2) void out_mma(
    const float* __restrict__ bo, float* __restrict__ out)
{
    extern __shared__ uint32_t sm[];
    const int tid = threadIdx.x, lane = tid & 31, wid = tid >> 5;
    const int c = lane & 3, g = lane >> 2;
    const int mw = (wid & 1) * 64, nw = (wid >> 1) * 64;

    const int m0 = blockIdx.x * 128;
    const int bb = m0 >> 11;
    const int l0 = m0 & (LEN - 1);
    const int n0 = blockIdx.y * 128;

    const uint32_t sbase = smem_u32(sm);
    const int kk0 = tid >> 5, m4s = (tid & 31) * 4;
    const uint32_t sdst = (uint32_t)(kk0 * POB + m4s) * 4;
    const uint32_t* aS = g_atth + m0 + (size_t)kk0 * MTOT + m4s;
    const uint32_t* bS = g_woh + n0 + (size_t)kk0 * DOUT + m4s;

    const uint32_t aA[2] = {sbase, sbase + OBSZ * 4};
    const uint32_t bA[2] = {sbase + 2 * OBSZ * 4, sbase + 3 * OBSZ * 4};

#define O_ISSUE(buf, k0p)                                                     \
    {                                                                         \
        _Pragma("unroll") for (int j = 0; j < 4; j++) {                       \
            cpa16(aA[buf] + sdst + j * (4 * POB * 4),                         \
                  aS + (size_t)((k0p) + 4 * j) * MTOT);                       \
            cpa16(bA[buf] + sdst + j * (4 * POB * 4),                         \
                  bS + (size_t)((k0p) + 4 * j) * DOUT);                       \
        }                                                                     \
        CP_COMMIT();                                                          \
    }

    float acc[4][8][4];
#pragma unroll
    for (int i = 0; i < 4; i++)
#pragma unroll
        for (int j = 0; j < 8; j++)
#pragma unroll
            for (int r = 0; r < 4; r++) acc[i][j][r] = 0.f;

    const int NCH = (DQKV / 2) / BKP;   // 16 chunks
    O_ISSUE(0, 0);
    for (int cc = 0; cc < NCH; cc++) {
        const int cur = cc & 1;
        if (cc + 1 < NCH) { O_ISSUE(cur ^ 1, (cc + 1) * BKP); CP_WAIT(1); }
        else              { CP_WAIT(0); }
        __syncthreads();
        mma_chunk64(sm + cur * OBSZ, sm + (2 + cur) * OBSZ, acc, mw, nw, c, g);
        __syncthreads();
    }
#undef O_ISSUE

    // Epilogue: two 64-n halves through smem bounce [n][m] (fp32, pitch 132)
    float* ep = (float*)sm;   // 64*132*4 = 33792 B <= SMEM_G
#pragma unroll
    for (int h = 0; h < 2; h++) {
        if ((nw >> 6) == h) {
#pragma unroll
            for (int fm = 0; fm < 4; fm++)
#pragma unroll
                for (int fn = 0; fn < 8; fn++) {
                    int nrel = fn * 8 + c * 2;
                    int mrel = mw + fm * 16 + g;
                    ep[nrel * EPPO + mrel]           = acc[fm][fn][0];
                    ep[(nrel + 1) * EPPO + mrel]     = acc[fm][fn][1];
                    ep[nrel * EPPO + mrel + 8]       = acc[fm][fn][2];
                    ep[(nrel + 1) * EPPO + mrel + 8] = acc[fm][fn][3];
                }
        }
        __syncthreads();
#pragma unroll
        for (int i = 0; i < 16; i++) {
            int f = tid + i * 128;
            int nr = f >> 5;
            int m4 = (f & 31) * 4;
            float4 v = *(float4*)&ep[nr * EPPO + m4];
            float bj = __ldg(bo + n0 + h * 64 + nr);
            v.x += bj; v.y += bj; v.z += bj; v.w += bj;
            *(float4*)(out + ((size_t)(bb * DOUT + n0 + h * 64 + nr)) * LEN
                       + l0 + m4) = v;
        }
        __syncthreads();
    }
}

// ---------------- launch ----------------
extern "C" void kernel_launch(void* const* d_in, const int* in_sizes, int n_in,
                              void* d_out, int out_size)
{
    const float* x  = (const float*)d_in[0];
    const float* Wq = (const float*)d_in[1];
    const float* bq = (const float*)d_in[2];
    const float* Wk = (const float*)d_in[3];
    const float* bk = (const float*)d_in[4];
    const float* Wv = (const float*)d_in[5];
    const float* bv = (const float*)d_in[6];
    const float* Wo = (const float*)d_in[7];
    const float* bo = (const float*)d_in[8];
    float* out = (float*)d_out;

    cudaFuncSetAttribute(qkv_mma, cudaFuncAttributeMaxDynamicSharedMemorySize, SMEM_G);
    cudaFuncSetAttribute(out_mma, cudaFuncAttributeMaxDynamicSharedMemorySize, SMEM_G);

    pack_all<<<(NTI + 255) / 256, 256>>>(x, Wq, Wk, Wv, Wo);
    qkv_mma<<<dim3(MTOT / 128, 12), 128, SMEM_G>>>(bq, bk, bv);
    attn_t<<<BATCH * NHEAD * (LEN / 32), 256>>>();
    out_mma<<<dim3(MTOT / 128, DOUT / 128), 128, SMEM_G>>>(bo, out);
}